// round 16
// baseline (speedup 1.0000x reference)
#include <cuda_runtime.h>
#include <cuda_fp16.h>
#include <math.h>
#include <stdint.h>

#define OBS0 80
#define OBS1 160
#define OBS2 384

// ---------------- device scratch ---------------------------------------------
__device__ float    g_WkT[256 * 256];
__device__ float    g_G[3 * 256 * 128];
__device__ float    g_c[64];
__device__ uint32_t g_Wo16[48 * 256];
__device__ uint32_t g_We16[80 * 256];
__device__ uint32_t g_Ws16[192 * 256];
__device__ uint32_t g_P16[128 * 256];
__device__ uint32_t g_H16[384 * 64];
__device__ float    g_u[32768 * 256];
__device__ float    g_hp[32768 * 64];
__device__ uint32_t g_sa16[32768 * 128];

// ---------------- helpers ------------------------------------------------------
__device__ __forceinline__ uint32_t pk(float lo, float hi) {
    uint32_t r; asm("cvt.rn.f16x2.f32 %0, %1, %2;" : "=r"(r) : "f"(hi), "f"(lo)); return r;
}
__device__ __forceinline__ float upksum(uint32_t v) {
    __half2 h = *(__half2*)&v;
    float2 f = __half22float2(h);
    return f.x + f.y;
}
__device__ __forceinline__ void mma16(float c[4], const uint32_t a[4], const uint32_t b[2]) {
    asm volatile("mma.sync.aligned.m16n8k16.row.col.f32.f16.f16.f32 "
        "{%0,%1,%2,%3},{%4,%5,%6,%7},{%8,%9},{%0,%1,%2,%3};"
        : "+f"(c[0]), "+f"(c[1]), "+f"(c[2]), "+f"(c[3])
        : "r"(a[0]), "r"(a[1]), "r"(a[2]), "r"(a[3]), "r"(b[0]), "r"(b[1]));
}
__device__ __forceinline__ void cpasync16(uint32_t dst, const void* src) {
    asm volatile("cp.async.cg.shared.global [%0], [%1], 16;" :: "r"(dst), "l"(src));
}
#define CP_COMMIT() asm volatile("cp.async.commit_group;" ::: "memory")
#define CP_WAIT1()  asm volatile("cp.async.wait_group 1;" ::: "memory")
#define CP_WAIT0()  asm volatile("cp.async.wait_group 0;" ::: "memory")
__device__ __forceinline__ uint32_t smem_u32(const void* p) {
    uint32_t a;
    asm("{ .reg .u64 t; cvta.to.shared.u64 t, %1; cvt.u32.u64 %0, t; }" : "=r"(a) : "l"(p));
    return a;
}

// scalar-LDS GEMM: A packed pairs in smem, B packed pairs in gmem
template<int KT, int MT, int NT>
__device__ __forceinline__ void gemmMN(const uint32_t* As, int sA,
                                       const uint32_t* __restrict__ Bg, int ldb, int n0,
                                       float acc[MT][NT][4], int g, int t) {
#pragma unroll
    for (int k = 0; k < KT; k++) {
        int kb = k * 8;
        uint32_t b0[NT], b1[NT];
#pragma unroll
        for (int n = 0; n < NT; n++) {
            b0[n] = Bg[(size_t)(kb + t) * ldb + n0 + n * 8 + g];
            b1[n] = Bg[(size_t)(kb + t + 4) * ldb + n0 + n * 8 + g];
        }
#pragma unroll
        for (int m = 0; m < MT; m++) {
            int r0 = m * 16 + g;
            uint32_t a[4];
            a[0] = As[r0 * sA + kb + t];
            a[1] = As[(r0 + 8) * sA + kb + t];
            a[2] = As[r0 * sA + kb + t + 4];
            a[3] = As[(r0 + 8) * sA + kb + t + 4];
#pragma unroll
            for (int n = 0; n < NT; n++) {
                uint32_t bb[2] = { b0[n], b1[n] };
                mma16(acc[m][n], a, bb);
            }
        }
    }
}

// ---------------- precompute (2 launches, unchanged R15) ------------------------
__global__ void pre1(const float* __restrict__ Wk, const float* __restrict__ Wo,
                     const float* __restrict__ We, const float* __restrict__ Ws,
                     const float* __restrict__ Wcv, const float* __restrict__ W_out) {
    __shared__ float row[256];
    int bid = blockIdx.x, tid = threadIdx.x;
    if (bid < 256) {
        int i = bid * 256 + tid;
        { int t = i >> 8, d = i & 255; g_WkT[t * 256 + d] = Wk[d * 256 + t]; }
        if (i < 192 * 256) {
            int kp = i >> 8, n = i & 255;
            g_Ws16[i] = pk(Ws[(size_t)(2 * kp) * 256 + n], Ws[(size_t)(2 * kp + 1) * 256 + n]);
        }
        if (i < 48 * 256) {
            int kp = i >> 8, n = i & 255;
            g_Wo16[i] = (kp < 40)
                ? pk(Wo[(size_t)(2 * kp) * 256 + n], Wo[(size_t)(2 * kp + 1) * 256 + n])
                : 0u;
        }
        if (i < 80 * 256) {
            int kp = i >> 8, n = i & 255;
            g_We16[i] = pk(We[(size_t)(2 * kp) * 256 + n], We[(size_t)(2 * kp + 1) * 256 + n]);
        }
    } else {
        int idx = bid - 256, h = idx >> 8, dd = idx & 255;
        row[tid] = Wcv[dd * 256 + tid];
        __syncthreads();
        if (tid < 128) {
            float acc = 0.f;
#pragma unroll 8
            for (int e = 0; e < 256; e++)
                acc = fmaf(row[e], W_out[(h * 256 + e) * 128 + tid], acc);
            g_G[(h * 256 + dd) * 128 + tid] = acc;
        }
    }
}

__global__ void pre2(const float* __restrict__ Wq, const float* __restrict__ Wv,
                     const float* __restrict__ W_j1,
                     const float* __restrict__ b_out, const float* __restrict__ b_j1) {
    __shared__ float sh[768];
    int bid = blockIdx.x, tid = threadIdx.x;
    if (bid < 128) {
        sh[tid]       = Wq[(size_t)(2 * bid) * 256 + tid];
        sh[256 + tid] = Wq[(size_t)(2 * bid + 1) * 256 + tid];
        __syncthreads();
        float a0 = 0.f, a1 = 0.f;
#pragma unroll 8
        for (int t2 = 0; t2 < 256; t2++) {
            float wv = g_WkT[t2 * 256 + tid];
            a0 = fmaf(sh[t2], wv, a0);
            a1 = fmaf(sh[256 + t2], wv, a1);
        }
        g_P16[bid * 256 + tid] = pk(a0, a1);
    } else if (bid < 384) {
        int kp = bid - 128;
        if (tid < 128) sh[tid] = g_G[(size_t)(2 * kp) * 128 + tid];
        else           sh[tid] = g_G[(size_t)(2 * kp + 1) * 128 + (tid - 128)];
        __syncthreads();
        if (tid < 64) {
            float a0 = 0.f, a1 = 0.f;
#pragma unroll 8
            for (int m = 0; m < 128; m++) {
                float w1 = W_j1[m * 64 + tid];
                a0 = fmaf(sh[m], w1, a0);
                a1 = fmaf(sh[128 + m], w1, a1);
            }
            g_H16[kp * 64 + tid] = pk(a0, a1);
        }
    } else if (bid < 512) {
        int kp = bid - 384;
        sh[tid]       = Wv[(size_t)(2 * kp) * 256 + tid];
        sh[256 + tid] = Wv[(size_t)(2 * kp + 1) * 256 + tid];
        __syncthreads();
        {
            int c2 = tid & 127;
            const float* wvr = (tid < 128) ? sh : sh + 256;
            float acc = 0.f;
#pragma unroll 8
            for (int e = 0; e < 256; e++)
                acc = fmaf(wvr[e], g_G[(size_t)(512 + e) * 128 + c2], acc);
            sh[512 + (tid < 128 ? 0 : 128) + c2] = acc;
        }
        __syncthreads();
        if (tid < 64) {
            float a0 = 0.f, a1 = 0.f;
#pragma unroll 8
            for (int m = 0; m < 128; m++) {
                float w1 = W_j1[m * 64 + tid];
                a0 = fmaf(sh[512 + m], w1, a0);
                a1 = fmaf(sh[640 + m], w1, a1);
            }
            g_H16[(256 + kp) * 64 + tid] = pk(a0, a1);
        }
    } else {
        if (tid < 64) {
            float acc = b_j1[tid];
#pragma unroll 8
            for (int m = 0; m < 128; m++) acc = fmaf(b_out[m], W_j1[m * 64 + tid], acc);
            g_c[tid] = acc;
        }
    }
}

// =============== K1: embeds -> u, hp  (3-buffer ring, distance-2; R15) =========
#define K1_S   0
#define K1_E   5376
#define K1_B   13824
#define K1_W   (13824 + 3 * 4224)
#define K1_BYTES (K1_W * 4)
#define K1BSTG (16 * 264)

extern __shared__ uint32_t smw[];

__device__ __forceinline__ const uint32_t* k1_bsrc(int c) {
    if (c < 5)  return g_We16 + (size_t)c * 16 * 256;
    if (c < 8)  return g_Wo16 + (size_t)(c - 5) * 16 * 256;
    return g_P16 + (size_t)(c - 8) * 16 * 256;
}

__global__ void __launch_bounds__(256, 2)
k1_embed(const float* __restrict__ state0, const float* __restrict__ state1,
         const float* __restrict__ b_own, const float* __restrict__ b_env) {
    uint32_t* S   = smw + K1_S;
    uint32_t* E   = smw + K1_E;
    uint32_t* Bst = smw + K1_B;
    const int tid = threadIdx.x;
    const int w = tid >> 5, lane = tid & 31;
    const int g = lane >> 2, t = lane & 3;
    const int bi = blockIdx.x * 64;
    const int n0 = w * 32;
    const uint32_t smbase = smem_u32(smw);

#pragma unroll
    for (int pc = 0; pc < 2; pc++) {
        uint32_t bb = smbase + (K1_B + pc * K1BSTG) * 4;
        const uint32_t* src = k1_bsrc(pc);
#pragma unroll
        for (int it = 0; it < 4; it++) {
            int idx = tid + it * 256;
            int row = idx >> 6, c4 = idx & 63;
            cpasync16(bb + (row * 264 + c4 * 4) * 4, src + (size_t)row * 256 + c4 * 4);
        }
        CP_COMMIT();
    }
    for (int i = tid; i < 64 * 80; i += 256) {
        int r = i / 80, kp = i % 80;
        float2 v = *(const float2*)(state1 + (size_t)(bi + r) * OBS1 + 2 * kp);
        S[r * 84 + kp] = pk(v.x, v.y);
    }

    float acc_hp[4][1][4];
#pragma unroll
    for (int m = 0; m < 4; m++)
#pragma unroll
        for (int j = 0; j < 4; j++) acc_hp[m][0][j] = 0.f;

    float accG[4][4][4];
#pragma unroll
    for (int m = 0; m < 4; m++)
#pragma unroll
        for (int n = 0; n < 4; n++)
#pragma unroll
            for (int j = 0; j < 4; j++) accG[m][n][j] = 0.f;

    for (int c = 0; c < 16; c++) {
        if (c < 15) CP_WAIT1(); else CP_WAIT0();
        __syncthreads();
        if (c + 2 < 16) {
            uint32_t bb = smbase + (K1_B + ((c + 2) % 3) * K1BSTG) * 4;
            const uint32_t* src = k1_bsrc(c + 2);
#pragma unroll
            for (int it = 0; it < 4; it++) {
                int idx = tid + it * 256;
                int row = idx >> 6, c4 = idx & 63;
                cpasync16(bb + (row * 264 + c4 * 4) * 4, src + (size_t)row * 256 + c4 * 4);
            }
            CP_COMMIT();
        }
        const uint32_t* Bc = Bst + (c % 3) * K1BSTG;
        const uint32_t* As; int sA, cb;
        if (c < 5)      { As = S; sA = 84;  cb = c; }
        else if (c < 8) { As = S; sA = 52;  cb = c - 5; }
        else            { As = E; sA = 132; cb = c - 8; }
#pragma unroll
        for (int ks = 0; ks < 2; ks++) {
            int kb = ks * 8;
            int ak = cb * 16 + kb;
            uint32_t b0[4], b1[4];
#pragma unroll
            for (int n = 0; n < 4; n++) {
                b0[n] = Bc[(kb + t) * 264 + n0 + n * 8 + g];
                b1[n] = Bc[(kb + t + 4) * 264 + n0 + n * 8 + g];
            }
#pragma unroll
            for (int m = 0; m < 4; m++) {
                int r0 = m * 16 + g;
                uint32_t a[4];
                a[0] = As[r0 * sA + ak + t];
                a[1] = As[(r0 + 8) * sA + ak + t];
                a[2] = As[r0 * sA + ak + t + 4];
                a[3] = As[(r0 + 8) * sA + ak + t + 4];
#pragma unroll
                for (int n = 0; n < 4; n++) {
                    uint32_t bb2[2] = { b0[n], b1[n] };
                    mma16(accG[m][n], a, bb2);
                }
            }
        }

        if (c == 4) {
#pragma unroll
            for (int m = 0; m < 4; m++)
#pragma unroll
                for (int n = 0; n < 4; n++) {
                    int col = n0 + n * 8 + 2 * t, r0 = m * 16 + g, cp = col >> 1;
                    float bb0 = b_env[col], bb1 = b_env[col + 1];
                    E[r0 * 132 + cp]       = pk(fmaxf(accG[m][n][0] + bb0, 0.f),
                                                fmaxf(accG[m][n][1] + bb1, 0.f));
                    E[(r0 + 8) * 132 + cp] = pk(fmaxf(accG[m][n][2] + bb0, 0.f),
                                                fmaxf(accG[m][n][3] + bb1, 0.f));
                }
            __syncthreads();
            gemmMN<16, 4, 1>(E, 132, g_H16 + 128 * 64, 64, w * 8, acc_hp, g, t);
            for (int i = tid; i < 64 * 52; i += 256) {
                int r = i / 52, kp = i % 52;
                uint32_t v = 0;
                if (kp < 40) {
                    float2 f = *(const float2*)(state0 + (size_t)(bi + r) * OBS0 + 2 * kp);
                    v = pk(f.x, f.y);
                }
                S[r * 52 + kp] = v;
            }
#pragma unroll
            for (int m = 0; m < 4; m++)
#pragma unroll
                for (int n = 0; n < 4; n++)
#pragma unroll
                    for (int j = 0; j < 4; j++) accG[m][n][j] = 0.f;
        }
        if (c == 7) {
#pragma unroll
            for (int m = 0; m < 4; m++)
#pragma unroll
                for (int n = 0; n < 4; n++) {
                    int col = n0 + n * 8 + 2 * t, r0 = m * 16 + g, cp = col >> 1;
                    float bb0 = b_own[col], bb1 = b_own[col + 1];
                    E[r0 * 132 + cp]       = pk(fmaxf(accG[m][n][0] + bb0, 0.f),
                                                fmaxf(accG[m][n][1] + bb1, 0.f));
                    E[(r0 + 8) * 132 + cp] = pk(fmaxf(accG[m][n][2] + bb0, 0.f),
                                                fmaxf(accG[m][n][3] + bb1, 0.f));
                }
            __syncthreads();
            gemmMN<16, 4, 1>(E, 132, g_H16, 64, w * 8, acc_hp, g, t);
            {
                int col = w * 8 + 2 * t;
#pragma unroll
                for (int m = 0; m < 4; m++) {
                    int r0 = bi + m * 16 + g;
                    *(float2*)(g_hp + (size_t)r0 * 64 + col) =
                        make_float2(acc_hp[m][0][0], acc_hp[m][0][1]);
                    *(float2*)(g_hp + (size_t)(r0 + 8) * 64 + col) =
                        make_float2(acc_hp[m][0][2], acc_hp[m][0][3]);
                }
            }
#pragma unroll
            for (int m = 0; m < 4; m++)
#pragma unroll
                for (int n = 0; n < 4; n++)
#pragma unroll
                    for (int j = 0; j < 4; j++) accG[m][n][j] = 0.f;
        }
    }

#pragma unroll
    for (int m = 0; m < 4; m++)
#pragma unroll
        for (int n = 0; n < 4; n++) {
            int col = n0 + n * 8 + 2 * t, r0 = bi + m * 16 + g;
            *(float2*)(g_u + (size_t)r0 * 256 + col) =
                make_float2(accG[m][n][0], accG[m][n][1]);
            *(float2*)(g_u + (size_t)(r0 + 8) * 256 + col) =
                make_float2(accG[m][n][2], accG[m][n][3]);
        }
}

// =============== K2: S GEMM + attention (M=128/CTA, 256 thr, 1 CTA/SM) =========
// words: A 128x196=25088 | B 2x(16x264)=8448 | U 16x260=4160 | msum/sc/al 3x128 | bias 256
#define K2_A   0
#define K2_B   25088
#define K2_U   33536
#define K2_MS  37696
#define K2_SC  37824
#define K2_AL  37952
#define K2_BI  38080
#define K2_W   38336
#define K2_BYTES (K2_W * 4)
#define BSTG   (16 * 264)

__global__ void __launch_bounds__(256, 1)
k2_attn(const float* __restrict__ state2, const float* __restrict__ b_sur) {
    uint32_t* A   = smw + K2_A;
    uint32_t* Bst = smw + K2_B;
    float* U    = (float*)(smw + K2_U);
    float* msum = (float*)(smw + K2_MS);
    float* sc   = (float*)(smw + K2_SC);
    float* al   = (float*)(smw + K2_AL);
    float* bias = (float*)(smw + K2_BI);

    const int tid = threadIdx.x;
    const int w = tid >> 5, lane = tid & 31;
    const int g = lane >> 2, t = lane & 3;
    const int mw = w >> 2, nw = w & 3;       // 2 x 4 warp grid
    const int n0 = nw * 64;
    const int bi = blockIdx.x * 16;          // 16 batches
    const uint32_t smbase = smem_u32(smw);

    if (tid < 128) { msum[tid] = 0.f; sc[tid] = 0.f; }
    bias[tid] = b_sur[tid];

    // prefetch B stage 0
    {
        uint32_t bb = smbase + K2_B * 4;
#pragma unroll
        for (int it = 0; it < 4; it++) {
            int idx = tid + it * 256;
            int row = idx >> 6, c4 = idx & 63;
            cpasync16(bb + (row * 264 + c4 * 4) * 4, g_Ws16 + (size_t)row * 256 + c4 * 4);
        }
        CP_COMMIT();
    }
    // load U (16 rows)
#pragma unroll
    for (int it = 0; it < 4; it++) {
        int idx = tid + it * 256;
        int row = idx >> 6, c4 = idx & 63;
        *(float4*)(U + row * 260 + c4 * 4) =
            *(const float4*)(g_u + (size_t)(bi + row) * 256 + c4 * 4);
    }
    // load + pack full A (128 rows x 192 pairs)
#pragma unroll
    for (int it = 0; it < 24; it++) {
        int idx = tid + it * 256;
        int r = idx / 48, c8 = idx % 48;
        const float* p = state2 + (size_t)(bi * 8 + r) * OBS2 + c8 * 8;
        float4 v0 = *(const float4*)p;
        float4 v1 = *(const float4*)(p + 4);
        uint4 tv = make_uint4(pk(v0.x, v0.y), pk(v0.z, v0.w), pk(v1.x, v1.y), pk(v1.z, v1.w));
        *(uint4*)(A + r * 196 + c8 * 4) = tv;
    }
    __syncthreads();
    // msum: warp w owns rows w*16..w*16+15
    for (int i = 0; i < 16; i++) {
        int row = w * 16 + i;
        float s = 0.f;
#pragma unroll
        for (int j = 0; j < 6; j++) s += upksum(A[row * 196 + lane + 32 * j]);
#pragma unroll
        for (int off = 16; off > 0; off >>= 1) s += __shfl_xor_sync(0xffffffffu, s, off);
        if (lane == 0) msum[row] = s;
    }

    float accS[4][8][4];
#pragma unroll
    for (int m = 0; m < 4; m++)
#pragma unroll
        for (int n = 0; n < 8; n++)
#pragma unroll
            for (int j = 0; j < 4; j++) accS[m][n][j] = 0.f;

    for (int s = 0; s < 12; s++) {
        if (s + 1 < 12) {
            uint32_t bb = smbase + (K2_B + ((s + 1) & 1) * BSTG) * 4;
            size_t k0 = (size_t)(s + 1) * 16;
#pragma unroll
            for (int it = 0; it < 4; it++) {
                int idx = tid + it * 256;
                int row = idx >> 6, c4 = idx & 63;
                cpasync16(bb + (row * 264 + c4 * 4) * 4, g_Ws16 + (k0 + row) * 256 + c4 * 4);
            }
            CP_COMMIT();
            CP_WAIT1();
        } else {
            CP_WAIT0();
        }
        __syncthreads();
        const uint32_t* Bc = Bst + (s & 1) * BSTG;
#pragma unroll
        for (int ks = 0; ks < 2; ks++) {
            int kb = ks * 8;
            int ak = s * 16 + kb;
            uint32_t b0[8], b1[8];
#pragma unroll
            for (int n = 0; n < 8; n++) {
                b0[n] = Bc[(kb + t) * 264 + n0 + n * 8 + g];
                b1[n] = Bc[(kb + t + 4) * 264 + n0 + n * 8 + g];
            }
#pragma unroll
            for (int m = 0; m < 4; m++) {
                int r0 = mw * 64 + m * 16 + g;
                uint32_t a[4];
                a[0] = A[r0 * 196 + ak + t];
                a[1] = A[(r0 + 8) * 196 + ak + t];
                a[2] = A[r0 * 196 + ak + t + 4];
                a[3] = A[(r0 + 8) * 196 + ak + t + 4];
#pragma unroll
                for (int n = 0; n < 8; n++) {
                    uint32_t bb2[2] = { b0[n], b1[n] };
                    mma16(accS[m][n], a, bb2);
                }
            }
        }
        __syncthreads();
    }

    // bias + relu
#pragma unroll
    for (int m = 0; m < 4; m++)
#pragma unroll
        for (int n = 0; n < 8; n++) {
            int col = n0 + n * 8 + 2 * t;
            float bb0 = bias[col], bb1 = bias[col + 1];
            accS[m][n][0] = fmaxf(accS[m][n][0] + bb0, 0.f);
            accS[m][n][1] = fmaxf(accS[m][n][1] + bb1, 0.f);
            accS[m][n][2] = fmaxf(accS[m][n][2] + bb0, 0.f);
            accS[m][n][3] = fmaxf(accS[m][n][3] + bb1, 0.f);
        }

    // score: rows mw*64 + m*16 + g  (batch 8mw+2m), +8 (batch 8mw+2m+1)
    {
        float sp[8];
#pragma unroll
        for (int i = 0; i < 8; i++) sp[i] = 0.f;
#pragma unroll
        for (int m = 0; m < 4; m++) {
            int bat = 8 * mw + 2 * m;
#pragma unroll
            for (int n = 0; n < 8; n++) {
                int col = n0 + n * 8 + 2 * t;
                sp[2 * m]     += accS[m][n][0] * U[bat * 260 + col]
                               + accS[m][n][1] * U[bat * 260 + col + 1];
                sp[2 * m + 1] += accS[m][n][2] * U[(bat + 1) * 260 + col]
                               + accS[m][n][3] * U[(bat + 1) * 260 + col + 1];
            }
        }
#pragma unroll
        for (int i = 0; i < 8; i++) {
            sp[i] += __shfl_xor_sync(0xffffffffu, sp[i], 1);
            sp[i] += __shfl_xor_sync(0xffffffffu, sp[i], 2);
        }
        if (t == 0) {
#pragma unroll
            for (int m = 0; m < 4; m++) {
                atomicAdd(&sc[64 * mw + 16 * m + g], sp[2 * m]);
                atomicAdd(&sc[64 * mw + 16 * m + 8 + g], sp[2 * m + 1]);
            }
        }
    }
    __syncthreads();

    // mask + softmax over K=8 (128 rows)
    if (tid < 128) {
        float s = (msum[tid] != 0.f) ? sc[tid] * 0.0625f : -INFINITY;
        float m = s;
#pragma unroll
        for (int off = 1; off < 8; off <<= 1)
            m = fmaxf(m, __shfl_xor_sync(0xffffffffu, m, off));
        float e = (s == -INFINITY) ? 0.f : expf(s - m);
        float ssum = e;
#pragma unroll
        for (int off = 1; off < 8; off <<= 1)
            ssum += __shfl_xor_sync(0xffffffffu, ssum, off);
        al[tid] = e / ssum;
    }
    __syncthreads();

    // s_att -> g_sa16 packed
#pragma unroll
    for (int m = 0; m < 4; m++) {
        float a0 = al[64 * mw + 16 * m + g];
        float a1 = al[64 * mw + 16 * m + 8 + g];
        float v[8][4];
#pragma unroll
        for (int n = 0; n < 8; n++) {
            v[n][0] = a0 * accS[m][n][0];
            v[n][1] = a0 * accS[m][n][1];
            v[n][2] = a1 * accS[m][n][2];
            v[n][3] = a1 * accS[m][n][3];
        }
#pragma unroll
        for (int n = 0; n < 8; n++)
#pragma unroll
            for (int j = 0; j < 4; j++) {
                v[n][j] += __shfl_xor_sync(0xffffffffu, v[n][j], 4);
                v[n][j] += __shfl_xor_sync(0xffffffffu, v[n][j], 8);
                v[n][j] += __shfl_xor_sync(0xffffffffu, v[n][j], 16);
            }
        if (g == 0) {
            int bat = 8 * mw + 2 * m;
#pragma unroll
            for (int n = 0; n < 8; n++) {
                int cp = nw * 32 + n * 4 + t;
                g_sa16[(size_t)(bi + bat) * 128 + cp]     = pk(v[n][0], v[n][1]);
                g_sa16[(size_t)(bi + bat + 1) * 128 + cp] = pk(v[n][2], v[n][3]);
            }
        }
    }
}

// =============== K3: tail -> out (unchanged) ====================================
#define K3_SA   0
#define K3_PART 16896
#define K3_W    (16896 + 1024)
#define K3_BYTES (K3_W * 4)

__global__ void __launch_bounds__(256, 1)
k3_tail(const float* __restrict__ W_j2, const float* __restrict__ b_j2,
        float* __restrict__ out) {
    uint32_t* SA = smw + K3_SA;
    float* part  = (float*)(smw + K3_PART);
    const int tid = threadIdx.x;
    const int w = tid >> 5, lane = tid & 31;
    const int g = lane >> 2, t = lane & 3;
    const int bi = blockIdx.x * 128;

#pragma unroll
    for (int it = 0; it < 16; it++) {
        int idx = tid + it * 256;
        int row = idx >> 5, c4 = idx & 31;
        *(uint4*)(SA + row * 132 + c4 * 4) =
            *(const uint4*)(g_sa16 + (size_t)(bi + row) * 128 + c4 * 4);
    }
    __syncthreads();

    float acc[8][1][4];
#pragma unroll
    for (int m = 0; m < 8; m++)
#pragma unroll
        for (int j = 0; j < 4; j++) acc[m][0][j] = 0.f;
    gemmMN<16, 8, 1>(SA, 132, g_H16 + 256 * 64, 64, w * 8, acc, g, t);

    {
        int col = w * 8 + 2 * t;
        float c0 = g_c[col], c1 = g_c[col + 1];
        float wj0 = W_j2[col], wj1 = W_j2[col + 1];
#pragma unroll
        for (int m = 0; m < 8; m++) {
            int r0 = m * 16 + g, r1 = r0 + 8;
            float2 hp0 = *(const float2*)(g_hp + (size_t)(bi + r0) * 64 + col);
            float2 hp1 = *(const float2*)(g_hp + (size_t)(bi + r1) * 64 + col);
            float h00 = fmaxf(acc[m][0][0] + hp0.x + c0, 0.f);
            float h01 = fmaxf(acc[m][0][1] + hp0.y + c1, 0.f);
            float h10 = fmaxf(acc[m][0][2] + hp1.x + c0, 0.f);
            float h11 = fmaxf(acc[m][0][3] + hp1.y + c1, 0.f);
            float p0 = h00 * wj0 + h01 * wj1;
            float p1 = h10 * wj0 + h11 * wj1;
            p0 += __shfl_xor_sync(0xffffffffu, p0, 1);
            p0 += __shfl_xor_sync(0xffffffffu, p0, 2);
            p1 += __shfl_xor_sync(0xffffffffu, p1, 1);
            p1 += __shfl_xor_sync(0xffffffffu, p1, 2);
            if (t == 0) { part[r0 * 8 + w] = p0; part[r1 * 8 + w] = p1; }
        }
    }
    __syncthreads();
    if (tid < 128) {
        float s = 0.f;
#pragma unroll
        for (int i = 0; i < 8; i++) s += part[tid * 8 + i];
        out[bi + tid] = s + b_j2[0];
    }
}

// ---------------- launch ------------------------------------------------------------
extern "C" void kernel_launch(void* const* d_in, const int* in_sizes, int n_in,
                              void* d_out, int out_size) {
    const float* state0 = (const float*)d_in[0];
    const float* state1 = (const float*)d_in[1];
    const float* state2 = (const float*)d_in[2];
    const float* W_own  = (const float*)d_in[3];
    const float* b_own  = (const float*)d_in[4];
    const float* W_env  = (const float*)d_in[5];
    const float* b_env  = (const float*)d_in[6];
    const float* W_sur  = (const float*)d_in[7];
    const float* b_sur  = (const float*)d_in[8];
    const float* Wq     = (const float*)d_in[9];
    const float* Wk     = (const float*)d_in[10];
    const float* Wv     = (const float*)d_in[11];
    const float* Wcv    = (const float*)d_in[14];
    const float* W_out  = (const float*)d_in[15];
    const float* b_out  = (const float*)d_in[16];
    const float* W_j1   = (const float*)d_in[17];
    const float* b_j1   = (const float*)d_in[18];
    const float* W_j2   = (const float*)d_in[19];
    const float* b_j2   = (const float*)d_in[20];
    float* out = (float*)d_out;

    int B = in_sizes[0] / OBS0;

    cudaFuncSetAttribute(k1_embed, cudaFuncAttributeMaxDynamicSharedMemorySize, K1_BYTES);
    cudaFuncSetAttribute(k2_attn,  cudaFuncAttributeMaxDynamicSharedMemorySize, K2_BYTES);
    cudaFuncSetAttribute(k3_tail,  cudaFuncAttributeMaxDynamicSharedMemorySize, K3_BYTES);

    pre1<<<1024, 256>>>(Wk, W_own, W_env, W_sur, Wcv, W_out);
    pre2<<<513, 256>>>(Wq, Wv, W_j1, b_out, b_j1);
    k1_embed<<<B / 64, 256, K1_BYTES>>>(state0, state1, b_own, b_env);
    k2_attn<<<B / 16, 256, K2_BYTES>>>(state2, b_sur);  // 4th launch -> ncu
    k3_tail<<<B / 128, 256, K3_BYTES>>>(W_j2, b_j2, out);
}

// round 17
// speedup vs baseline: 1.1116x; 1.1116x over previous
#include <cuda_runtime.h>
#include <cuda_fp16.h>
#include <math.h>
#include <stdint.h>

#define OBS0 80
#define OBS1 160
#define OBS2 384

// ---------------- device scratch ---------------------------------------------
__device__ float    g_WkT[256 * 256];
__device__ float    g_G[3 * 256 * 128];
__device__ float    g_c[64];
__device__ uint32_t g_Wo16[48 * 256];
__device__ uint32_t g_We16[80 * 256];
__device__ uint32_t g_Ws16[192 * 256];
__device__ uint32_t g_P16[128 * 256];
__device__ uint32_t g_H16[384 * 64];
__device__ float    g_u[32768 * 256];
__device__ float    g_hp[32768 * 64];
__device__ uint32_t g_sa16[32768 * 128];

// ---------------- helpers ------------------------------------------------------
__device__ __forceinline__ uint32_t pk(float lo, float hi) {
    uint32_t r; asm("cvt.rn.f16x2.f32 %0, %1, %2;" : "=r"(r) : "f"(hi), "f"(lo)); return r;
}
__device__ __forceinline__ float upksum(uint32_t v) {
    __half2 h = *(__half2*)&v;
    float2 f = __half22float2(h);
    return f.x + f.y;
}
__device__ __forceinline__ void mma16(float c[4], const uint32_t a[4], const uint32_t b[2]) {
    asm volatile("mma.sync.aligned.m16n8k16.row.col.f32.f16.f16.f32 "
        "{%0,%1,%2,%3},{%4,%5,%6,%7},{%8,%9},{%0,%1,%2,%3};"
        : "+f"(c[0]), "+f"(c[1]), "+f"(c[2]), "+f"(c[3])
        : "r"(a[0]), "r"(a[1]), "r"(a[2]), "r"(a[3]), "r"(b[0]), "r"(b[1]));
}
__device__ __forceinline__ void cpasync16(uint32_t dst, const void* src) {
    asm volatile("cp.async.cg.shared.global [%0], [%1], 16;" :: "r"(dst), "l"(src));
}
#define CP_COMMIT() asm volatile("cp.async.commit_group;" ::: "memory")
#define CP_WAIT1()  asm volatile("cp.async.wait_group 1;" ::: "memory")
#define CP_WAIT0()  asm volatile("cp.async.wait_group 0;" ::: "memory")
__device__ __forceinline__ uint32_t smem_u32(const void* p) {
    uint32_t a;
    asm("{ .reg .u64 t; cvta.to.shared.u64 t, %1; cvt.u32.u64 %0, t; }" : "=r"(a) : "l"(p));
    return a;
}

// scalar-LDS GEMM: A packed pairs in smem, B packed pairs in gmem
template<int KT, int MT, int NT>
__device__ __forceinline__ void gemmMN(const uint32_t* As, int sA,
                                       const uint32_t* __restrict__ Bg, int ldb, int n0,
                                       float acc[MT][NT][4], int g, int t) {
#pragma unroll
    for (int k = 0; k < KT; k++) {
        int kb = k * 8;
        uint32_t b0[NT], b1[NT];
#pragma unroll
        for (int n = 0; n < NT; n++) {
            b0[n] = Bg[(size_t)(kb + t) * ldb + n0 + n * 8 + g];
            b1[n] = Bg[(size_t)(kb + t + 4) * ldb + n0 + n * 8 + g];
        }
#pragma unroll
        for (int m = 0; m < MT; m++) {
            int r0 = m * 16 + g;
            uint32_t a[4];
            a[0] = As[r0 * sA + kb + t];
            a[1] = As[(r0 + 8) * sA + kb + t];
            a[2] = As[r0 * sA + kb + t + 4];
            a[3] = As[(r0 + 8) * sA + kb + t + 4];
#pragma unroll
            for (int n = 0; n < NT; n++) {
                uint32_t bb[2] = { b0[n], b1[n] };
                mma16(acc[m][n], a, bb);
            }
        }
    }
}

// ---------------- precompute (2 launches, R15) ----------------------------------
__global__ void pre1(const float* __restrict__ Wk, const float* __restrict__ Wo,
                     const float* __restrict__ We, const float* __restrict__ Ws,
                     const float* __restrict__ Wcv, const float* __restrict__ W_out) {
    __shared__ float row[256];
    int bid = blockIdx.x, tid = threadIdx.x;
    if (bid < 256) {
        int i = bid * 256 + tid;
        { int t = i >> 8, d = i & 255; g_WkT[t * 256 + d] = Wk[d * 256 + t]; }
        if (i < 192 * 256) {
            int kp = i >> 8, n = i & 255;
            g_Ws16[i] = pk(Ws[(size_t)(2 * kp) * 256 + n], Ws[(size_t)(2 * kp + 1) * 256 + n]);
        }
        if (i < 48 * 256) {
            int kp = i >> 8, n = i & 255;
            g_Wo16[i] = (kp < 40)
                ? pk(Wo[(size_t)(2 * kp) * 256 + n], Wo[(size_t)(2 * kp + 1) * 256 + n])
                : 0u;
        }
        if (i < 80 * 256) {
            int kp = i >> 8, n = i & 255;
            g_We16[i] = pk(We[(size_t)(2 * kp) * 256 + n], We[(size_t)(2 * kp + 1) * 256 + n]);
        }
    } else {
        int idx = bid - 256, h = idx >> 8, dd = idx & 255;
        row[tid] = Wcv[dd * 256 + tid];
        __syncthreads();
        if (tid < 128) {
            float acc = 0.f;
#pragma unroll 8
            for (int e = 0; e < 256; e++)
                acc = fmaf(row[e], W_out[(h * 256 + e) * 128 + tid], acc);
            g_G[(h * 256 + dd) * 128 + tid] = acc;
        }
    }
}

__global__ void pre2(const float* __restrict__ Wq, const float* __restrict__ Wv,
                     const float* __restrict__ W_j1,
                     const float* __restrict__ b_out, const float* __restrict__ b_j1) {
    __shared__ float sh[768];
    int bid = blockIdx.x, tid = threadIdx.x;
    if (bid < 128) {
        sh[tid]       = Wq[(size_t)(2 * bid) * 256 + tid];
        sh[256 + tid] = Wq[(size_t)(2 * bid + 1) * 256 + tid];
        __syncthreads();
        float a0 = 0.f, a1 = 0.f;
#pragma unroll 8
        for (int t2 = 0; t2 < 256; t2++) {
            float wv = g_WkT[t2 * 256 + tid];
            a0 = fmaf(sh[t2], wv, a0);
            a1 = fmaf(sh[256 + t2], wv, a1);
        }
        g_P16[bid * 256 + tid] = pk(a0, a1);
    } else if (bid < 384) {
        int kp = bid - 128;
        if (tid < 128) sh[tid] = g_G[(size_t)(2 * kp) * 128 + tid];
        else           sh[tid] = g_G[(size_t)(2 * kp + 1) * 128 + (tid - 128)];
        __syncthreads();
        if (tid < 64) {
            float a0 = 0.f, a1 = 0.f;
#pragma unroll 8
            for (int m = 0; m < 128; m++) {
                float w1 = W_j1[m * 64 + tid];
                a0 = fmaf(sh[m], w1, a0);
                a1 = fmaf(sh[128 + m], w1, a1);
            }
            g_H16[kp * 64 + tid] = pk(a0, a1);
        }
    } else if (bid < 512) {
        int kp = bid - 384;
        sh[tid]       = Wv[(size_t)(2 * kp) * 256 + tid];
        sh[256 + tid] = Wv[(size_t)(2 * kp + 1) * 256 + tid];
        __syncthreads();
        {
            int c2 = tid & 127;
            const float* wvr = (tid < 128) ? sh : sh + 256;
            float acc = 0.f;
#pragma unroll 8
            for (int e = 0; e < 256; e++)
                acc = fmaf(wvr[e], g_G[(size_t)(512 + e) * 128 + c2], acc);
            sh[512 + (tid < 128 ? 0 : 128) + c2] = acc;
        }
        __syncthreads();
        if (tid < 64) {
            float a0 = 0.f, a1 = 0.f;
#pragma unroll 8
            for (int m = 0; m < 128; m++) {
                float w1 = W_j1[m * 64 + tid];
                a0 = fmaf(sh[512 + m], w1, a0);
                a1 = fmaf(sh[640 + m], w1, a1);
            }
            g_H16[(256 + kp) * 64 + tid] = pk(a0, a1);
        }
    } else {
        if (tid < 64) {
            float acc = b_j1[tid];
#pragma unroll 8
            for (int m = 0; m < 128; m++) acc = fmaf(b_out[m], W_j1[m * 64 + tid], acc);
            g_c[tid] = acc;
        }
    }
}

// =============== K1: embeds -> u, hp  (R13 exact; + launch_dependents) =========
#define K1_S   0
#define K1_E   5376
#define K1_B   13824
#define K1_W   (13824 + 8448)
#define K1_BYTES (K1_W * 4)
#define K1BSTG (16 * 264)

extern __shared__ uint32_t smw[];

__device__ __forceinline__ const uint32_t* k1_bsrc(int c) {
    if (c < 5)  return g_We16 + (size_t)c * 16 * 256;
    if (c < 8)  return g_Wo16 + (size_t)(c - 5) * 16 * 256;
    return g_P16 + (size_t)(c - 8) * 16 * 256;
}

__global__ void __launch_bounds__(256, 2)
k1_embed(const float* __restrict__ state0, const float* __restrict__ state1,
         const float* __restrict__ b_own, const float* __restrict__ b_env) {
    asm volatile("griddepcontrol.launch_dependents;");
    uint32_t* S   = smw + K1_S;
    uint32_t* E   = smw + K1_E;
    uint32_t* Bst = smw + K1_B;
    const int tid = threadIdx.x;
    const int w = tid >> 5, lane = tid & 31;
    const int g = lane >> 2, t = lane & 3;
    const int bi = blockIdx.x * 64;
    const int n0 = w * 32;
    const uint32_t smbase = smem_u32(smw);

    {
        uint32_t bb = smbase + K1_B * 4;
#pragma unroll
        for (int it = 0; it < 4; it++) {
            int idx = tid + it * 256;
            int row = idx >> 6, c4 = idx & 63;
            cpasync16(bb + (row * 264 + c4 * 4) * 4, g_We16 + (size_t)row * 256 + c4 * 4);
        }
        CP_COMMIT();
    }
    for (int i = tid; i < 64 * 80; i += 256) {
        int r = i / 80, kp = i % 80;
        float2 v = *(const float2*)(state1 + (size_t)(bi + r) * OBS1 + 2 * kp);
        S[r * 84 + kp] = pk(v.x, v.y);
    }

    float acc_hp[4][1][4];
#pragma unroll
    for (int m = 0; m < 4; m++)
#pragma unroll
        for (int j = 0; j < 4; j++) acc_hp[m][0][j] = 0.f;

    float accG[4][4][4];
#pragma unroll
    for (int m = 0; m < 4; m++)
#pragma unroll
        for (int n = 0; n < 4; n++)
#pragma unroll
            for (int j = 0; j < 4; j++) accG[m][n][j] = 0.f;

    for (int c = 0; c < 16; c++) {
        if (c + 1 < 16) {
            uint32_t bb = smbase + (K1_B + ((c + 1) & 1) * K1BSTG) * 4;
            const uint32_t* src = k1_bsrc(c + 1);
#pragma unroll
            for (int it = 0; it < 4; it++) {
                int idx = tid + it * 256;
                int row = idx >> 6, c4 = idx & 63;
                cpasync16(bb + (row * 264 + c4 * 4) * 4, src + (size_t)row * 256 + c4 * 4);
            }
            CP_COMMIT();
            CP_WAIT1();
        } else {
            CP_WAIT0();
        }
        __syncthreads();
        const uint32_t* Bc = Bst + (c & 1) * K1BSTG;
        const uint32_t* As; int sA, cb;
        if (c < 5)      { As = S; sA = 84;  cb = c; }
        else if (c < 8) { As = S; sA = 52;  cb = c - 5; }
        else            { As = E; sA = 132; cb = c - 8; }
#pragma unroll
        for (int ks = 0; ks < 2; ks++) {
            int kb = ks * 8;
            int ak = cb * 16 + kb;
            uint32_t b0[4], b1[4];
#pragma unroll
            for (int n = 0; n < 4; n++) {
                b0[n] = Bc[(kb + t) * 264 + n0 + n * 8 + g];
                b1[n] = Bc[(kb + t + 4) * 264 + n0 + n * 8 + g];
            }
#pragma unroll
            for (int m = 0; m < 4; m++) {
                int r0 = m * 16 + g;
                uint32_t a[4];
                a[0] = As[r0 * sA + ak + t];
                a[1] = As[(r0 + 8) * sA + ak + t];
                a[2] = As[r0 * sA + ak + t + 4];
                a[3] = As[(r0 + 8) * sA + ak + t + 4];
#pragma unroll
                for (int n = 0; n < 4; n++) {
                    uint32_t bb2[2] = { b0[n], b1[n] };
                    mma16(accG[m][n], a, bb2);
                }
            }
        }
        __syncthreads();

        if (c == 4) {
#pragma unroll
            for (int m = 0; m < 4; m++)
#pragma unroll
                for (int n = 0; n < 4; n++) {
                    int col = n0 + n * 8 + 2 * t, r0 = m * 16 + g, cp = col >> 1;
                    float bb0 = b_env[col], bb1 = b_env[col + 1];
                    E[r0 * 132 + cp]       = pk(fmaxf(accG[m][n][0] + bb0, 0.f),
                                                fmaxf(accG[m][n][1] + bb1, 0.f));
                    E[(r0 + 8) * 132 + cp] = pk(fmaxf(accG[m][n][2] + bb0, 0.f),
                                                fmaxf(accG[m][n][3] + bb1, 0.f));
                }
            __syncthreads();
            gemmMN<16, 4, 1>(E, 132, g_H16 + 128 * 64, 64, w * 8, acc_hp, g, t);
            for (int i = tid; i < 64 * 52; i += 256) {
                int r = i / 52, kp = i % 52;
                uint32_t v = 0;
                if (kp < 40) {
                    float2 f = *(const float2*)(state0 + (size_t)(bi + r) * OBS0 + 2 * kp);
                    v = pk(f.x, f.y);
                }
                S[r * 52 + kp] = v;
            }
#pragma unroll
            for (int m = 0; m < 4; m++)
#pragma unroll
                for (int n = 0; n < 4; n++)
#pragma unroll
                    for (int j = 0; j < 4; j++) accG[m][n][j] = 0.f;
        }
        if (c == 7) {
#pragma unroll
            for (int m = 0; m < 4; m++)
#pragma unroll
                for (int n = 0; n < 4; n++) {
                    int col = n0 + n * 8 + 2 * t, r0 = m * 16 + g, cp = col >> 1;
                    float bb0 = b_own[col], bb1 = b_own[col + 1];
                    E[r0 * 132 + cp]       = pk(fmaxf(accG[m][n][0] + bb0, 0.f),
                                                fmaxf(accG[m][n][1] + bb1, 0.f));
                    E[(r0 + 8) * 132 + cp] = pk(fmaxf(accG[m][n][2] + bb0, 0.f),
                                                fmaxf(accG[m][n][3] + bb1, 0.f));
                }
            __syncthreads();
            gemmMN<16, 4, 1>(E, 132, g_H16, 64, w * 8, acc_hp, g, t);
            {
                int col = w * 8 + 2 * t;
#pragma unroll
                for (int m = 0; m < 4; m++) {
                    int r0 = bi + m * 16 + g;
                    *(float2*)(g_hp + (size_t)r0 * 64 + col) =
                        make_float2(acc_hp[m][0][0], acc_hp[m][0][1]);
                    *(float2*)(g_hp + (size_t)(r0 + 8) * 64 + col) =
                        make_float2(acc_hp[m][0][2], acc_hp[m][0][3]);
                }
            }
#pragma unroll
            for (int m = 0; m < 4; m++)
#pragma unroll
                for (int n = 0; n < 4; n++)
#pragma unroll
                    for (int j = 0; j < 4; j++) accG[m][n][j] = 0.f;
        }
    }

#pragma unroll
    for (int m = 0; m < 4; m++)
#pragma unroll
        for (int n = 0; n < 4; n++) {
            int col = n0 + n * 8 + 2 * t, r0 = bi + m * 16 + g;
            *(float2*)(g_u + (size_t)r0 * 256 + col) =
                make_float2(accG[m][n][0], accG[m][n][1]);
            *(float2*)(g_u + (size_t)(r0 + 8) * 256 + col) =
                make_float2(accG[m][n][2], accG[m][n][3]);
        }
}

// =============== K2: S GEMM + attention (R9 exact; U deferred behind PDL wait) ==
#define K2_A   0
#define K2_B   12544
#define K2_U   20992
#define K2_MS  23072
#define K2_SC  23136
#define K2_AL  23200
#define K2_BI  23264
#define K2_W   23520
#define K2_BYTES (K2_W * 4)
#define BSTG   (16 * 264)

__global__ void __launch_bounds__(256, 2)
k2_attn(const float* __restrict__ state2, const float* __restrict__ b_sur) {
    uint32_t* A   = smw + K2_A;
    uint32_t* Bst = smw + K2_B;
    float* U    = (float*)(smw + K2_U);
    float* msum = (float*)(smw + K2_MS);
    float* sc   = (float*)(smw + K2_SC);
    float* al   = (float*)(smw + K2_AL);
    float* bias = (float*)(smw + K2_BI);

    const int tid = threadIdx.x;
    const int w = tid >> 5, lane = tid & 31;
    const int g = lane >> 2, t = lane & 3;
    const int mw = w >> 2, nw = w & 3;
    const int n0 = nw * 64;
    const int bi = blockIdx.x * 8;
    const uint32_t smbase = smem_u32(smw);

    if (tid < 64) { msum[tid] = 0.f; sc[tid] = 0.f; }
    bias[tid] = b_sur[tid];

    {
        uint32_t bb = smbase + K2_B * 4;
#pragma unroll
        for (int it = 0; it < 4; it++) {
            int idx = tid + it * 256;
            int row = idx >> 6, c4 = idx & 63;
            cpasync16(bb + (row * 264 + c4 * 4) * 4, g_Ws16 + (size_t)row * 256 + c4 * 4);
        }
        CP_COMMIT();
    }
    // load + pack full A (independent of k1)
#pragma unroll
    for (int it = 0; it < 12; it++) {
        int idx = tid + it * 256;
        int r = idx / 48, c8 = idx % 48;
        const float* p = state2 + (size_t)(bi * 8 + r) * OBS2 + c8 * 8;
        float4 v0 = *(const float4*)p;
        float4 v1 = *(const float4*)(p + 4);
        uint4 tv = make_uint4(pk(v0.x, v0.y), pk(v0.z, v0.w), pk(v1.x, v1.y), pk(v1.z, v1.w));
        *(uint4*)(A + r * 196 + c8 * 4) = tv;
    }
    __syncthreads();
    for (int i = 0; i < 8; i++) {
        int row = w * 8 + i;
        float s = 0.f;
#pragma unroll
        for (int j = 0; j < 6; j++) s += upksum(A[row * 196 + lane + 32 * j]);
#pragma unroll
        for (int off = 16; off > 0; off >>= 1) s += __shfl_xor_sync(0xffffffffu, s, off);
        if (lane == 0) msum[row] = s;
    }

    float accS[2][8][4];
#pragma unroll
    for (int m = 0; m < 2; m++)
#pragma unroll
        for (int n = 0; n < 8; n++)
#pragma unroll
            for (int j = 0; j < 4; j++) accS[m][n][j] = 0.f;

    for (int s = 0; s < 12; s++) {
        if (s + 1 < 12) {
            uint32_t bb = smbase + (K2_B + ((s + 1) & 1) * BSTG) * 4;
            size_t k0 = (size_t)(s + 1) * 16;
#pragma unroll
            for (int it = 0; it < 4; it++) {
                int idx = tid + it * 256;
                int row = idx >> 6, c4 = idx & 63;
                cpasync16(bb + (row * 264 + c4 * 4) * 4, g_Ws16 + (k0 + row) * 256 + c4 * 4);
            }
            CP_COMMIT();
            CP_WAIT1();
        } else {
            CP_WAIT0();
        }
        __syncthreads();
        const uint32_t* Bc = Bst + (s & 1) * BSTG;
#pragma unroll
        for (int ks = 0; ks < 2; ks++) {
            int kb = ks * 8;
            int ak = s * 16 + kb;
            uint32_t b0[8], b1[8];
#pragma unroll
            for (int n = 0; n < 8; n++) {
                b0[n] = Bc[(kb + t) * 264 + n0 + n * 8 + g];
                b1[n] = Bc[(kb + t + 4) * 264 + n0 + n * 8 + g];
            }
#pragma unroll
            for (int m = 0; m < 2; m++) {
                int r0 = mw * 32 + m * 16 + g;
                uint32_t a[4];
                a[0] = A[r0 * 196 + ak + t];
                a[1] = A[(r0 + 8) * 196 + ak + t];
                a[2] = A[r0 * 196 + ak + t + 4];
                a[3] = A[(r0 + 8) * 196 + ak + t + 4];
#pragma unroll
                for (int n = 0; n < 8; n++) {
                    uint32_t bb2[2] = { b0[n], b1[n] };
                    mma16(accS[m][n], a, bb2);
                }
            }
        }
        __syncthreads();
    }

    // bias + relu
#pragma unroll
    for (int m = 0; m < 2; m++)
#pragma unroll
        for (int n = 0; n < 8; n++) {
            int col = n0 + n * 8 + 2 * t;
            float bb0 = bias[col], bb1 = bias[col + 1];
            accS[m][n][0] = fmaxf(accS[m][n][0] + bb0, 0.f);
            accS[m][n][1] = fmaxf(accS[m][n][1] + bb1, 0.f);
            accS[m][n][2] = fmaxf(accS[m][n][2] + bb0, 0.f);
            accS[m][n][3] = fmaxf(accS[m][n][3] + bb1, 0.f);
        }

    // --- PDL: k1 results (g_u) needed from here on ---
    asm volatile("griddepcontrol.wait;" ::: "memory");
#pragma unroll
    for (int it = 0; it < 2; it++) {
        int idx = tid + it * 256;
        int row = idx >> 6, c4 = idx & 63;
        *(float4*)(U + row * 260 + c4 * 4) =
            *(const float4*)(g_u + (size_t)(bi + row) * 256 + c4 * 4);
    }
    __syncthreads();

    // score
    {
        float sp[4];
#pragma unroll
        for (int i = 0; i < 4; i++) sp[i] = 0.f;
#pragma unroll
        for (int m = 0; m < 2; m++) {
            int bat = 4 * mw + 2 * m;
#pragma unroll
            for (int n = 0; n < 8; n++) {
                int col = n0 + n * 8 + 2 * t;
                sp[2 * m]     += accS[m][n][0] * U[bat * 260 + col]
                               + accS[m][n][1] * U[bat * 260 + col + 1];
                sp[2 * m + 1] += accS[m][n][2] * U[(bat + 1) * 260 + col]
                               + accS[m][n][3] * U[(bat + 1) * 260 + col + 1];
            }
        }
#pragma unroll
        for (int i = 0; i < 4; i++) {
            sp[i] += __shfl_xor_sync(0xffffffffu, sp[i], 1);
            sp[i] += __shfl_xor_sync(0xffffffffu, sp[i], 2);
        }
        if (t == 0) {
#pragma unroll
            for (int m = 0; m < 2; m++) {
                atomicAdd(&sc[32 * mw + 16 * m + g], sp[2 * m]);
                atomicAdd(&sc[32 * mw + 16 * m + 8 + g], sp[2 * m + 1]);
            }
        }
    }
    __syncthreads();

    // mask + softmax over K=8
    if (tid < 64) {
        float s = (msum[tid] != 0.f) ? sc[tid] * 0.0625f : -INFINITY;
        float m = s;
#pragma unroll
        for (int off = 1; off < 8; off <<= 1)
            m = fmaxf(m, __shfl_xor_sync(0xffffffffu, m, off));
        float e = (s == -INFINITY) ? 0.f : expf(s - m);
        float ssum = e;
#pragma unroll
        for (int off = 1; off < 8; off <<= 1)
            ssum += __shfl_xor_sync(0xffffffffu, ssum, off);
        al[tid] = e / ssum;
    }
    __syncthreads();

    // s_att -> g_sa16
#pragma unroll
    for (int m = 0; m < 2; m++) {
        float a0 = al[32 * mw + 16 * m + g];
        float a1 = al[32 * mw + 16 * m + 8 + g];
        float v[8][4];
#pragma unroll
        for (int n = 0; n < 8; n++) {
            v[n][0] = a0 * accS[m][n][0];
            v[n][1] = a0 * accS[m][n][1];
            v[n][2] = a1 * accS[m][n][2];
            v[n][3] = a1 * accS[m][n][3];
        }
#pragma unroll
        for (int n = 0; n < 8; n++)
#pragma unroll
            for (int j = 0; j < 4; j++) {
                v[n][j] += __shfl_xor_sync(0xffffffffu, v[n][j], 4);
                v[n][j] += __shfl_xor_sync(0xffffffffu, v[n][j], 8);
                v[n][j] += __shfl_xor_sync(0xffffffffu, v[n][j], 16);
            }
        if (g == 0) {
            int bat = 4 * mw + 2 * m;
#pragma unroll
            for (int n = 0; n < 8; n++) {
                int cp = nw * 32 + n * 4 + t;
                g_sa16[(size_t)(bi + bat) * 128 + cp]     = pk(v[n][0], v[n][1]);
                g_sa16[(size_t)(bi + bat + 1) * 128 + cp] = pk(v[n][2], v[n][3]);
            }
        }
    }
}

// =============== K3: tail -> out (64 rows/CTA, 2 CTAs/SM) =======================
#define K3_SA   0
#define K3_PART 8448
#define K3_W    (8448 + 512)
#define K3_BYTES (K3_W * 4)

__global__ void __launch_bounds__(256, 2)
k3_tail(const float* __restrict__ W_j2, const float* __restrict__ b_j2,
        float* __restrict__ out) {
    uint32_t* SA = smw + K3_SA;
    float* part  = (float*)(smw + K3_PART);
    const int tid = threadIdx.x;
    const int w = tid >> 5, lane = tid & 31;
    const int g = lane >> 2, t = lane & 3;
    const int bi = blockIdx.x * 64;

#pragma unroll
    for (int it = 0; it < 8; it++) {
        int idx = tid + it * 256;                  // 0..2047 uint4
        int row = idx >> 5, c4 = idx & 31;
        *(uint4*)(SA + row * 132 + c4 * 4) =
            *(const uint4*)(g_sa16 + (size_t)(bi + row) * 128 + c4 * 4);
    }
    __syncthreads();

    float acc[4][1][4];
#pragma unroll
    for (int m = 0; m < 4; m++)
#pragma unroll
        for (int j = 0; j < 4; j++) acc[m][0][j] = 0.f;
    gemmMN<16, 4, 1>(SA, 132, g_H16 + 256 * 64, 64, w * 8, acc, g, t);

    {
        int col = w * 8 + 2 * t;
        float c0 = g_c[col], c1 = g_c[col + 1];
        float wj0 = W_j2[col], wj1 = W_j2[col + 1];
#pragma unroll
        for (int m = 0; m < 4; m++) {
            int r0 = m * 16 + g, r1 = r0 + 8;
            float2 hp0 = *(const float2*)(g_hp + (size_t)(bi + r0) * 64 + col);
            float2 hp1 = *(const float2*)(g_hp + (size_t)(bi + r1) * 64 + col);
            float h00 = fmaxf(acc[m][0][0] + hp0.x + c0, 0.f);
            float h01 = fmaxf(acc[m][0][1] + hp0.y + c1, 0.f);
            float h10 = fmaxf(acc[m][0][2] + hp1.x + c0, 0.f);
            float h11 = fmaxf(acc[m][0][3] + hp1.y + c1, 0.f);
            float p0 = h00 * wj0 + h01 * wj1;
            float p1 = h10 * wj0 + h11 * wj1;
            p0 += __shfl_xor_sync(0xffffffffu, p0, 1);
            p0 += __shfl_xor_sync(0xffffffffu, p0, 2);
            p1 += __shfl_xor_sync(0xffffffffu, p1, 1);
            p1 += __shfl_xor_sync(0xffffffffu, p1, 2);
            if (t == 0) { part[r0 * 8 + w] = p0; part[r1 * 8 + w] = p1; }
        }
    }
    __syncthreads();
    if (tid < 64) {
        float s = 0.f;
#pragma unroll
        for (int i = 0; i < 8; i++) s += part[tid * 8 + i];
        out[bi + tid] = s + b_j2[0];
    }
}

// ---------------- launch ------------------------------------------------------------
extern "C" void kernel_launch(void* const* d_in, const int* in_sizes, int n_in,
                              void* d_out, int out_size) {
    const float* state0 = (const float*)d_in[0];
    const float* state1 = (const float*)d_in[1];
    const float* state2 = (const float*)d_in[2];
    const float* W_own  = (const float*)d_in[3];
    const float* b_own  = (const float*)d_in[4];
    const float* W_env  = (const float*)d_in[5];
    const float* b_env  = (const float*)d_in[6];
    const float* W_sur  = (const float*)d_in[7];
    const float* b_sur  = (const float*)d_in[8];
    const float* Wq     = (const float*)d_in[9];
    const float* Wk     = (const float*)d_in[10];
    const float* Wv     = (const float*)d_in[11];
    const float* Wcv    = (const float*)d_in[14];
    const float* W_out  = (const float*)d_in[15];
    const float* b_out  = (const float*)d_in[16];
    const float* W_j1   = (const float*)d_in[17];
    const float* b_j1   = (const float*)d_in[18];
    const float* W_j2   = (const float*)d_in[19];
    const float* b_j2   = (const float*)d_in[20];
    float* out = (float*)d_out;

    int B = in_sizes[0] / OBS0;

    cudaFuncSetAttribute(k1_embed, cudaFuncAttributeMaxDynamicSharedMemorySize, K1_BYTES);
    cudaFuncSetAttribute(k2_attn,  cudaFuncAttributeMaxDynamicSharedMemorySize, K2_BYTES);
    cudaFuncSetAttribute(k3_tail,  cudaFuncAttributeMaxDynamicSharedMemorySize, K3_BYTES);

    pre1<<<1024, 256>>>(Wk, W_own, W_env, W_sur, Wcv, W_out);
    pre2<<<513, 256>>>(Wq, Wv, W_j1, b_out, b_j1);
    k1_embed<<<B / 64, 256, K1_BYTES>>>(state0, state1, b_own, b_env);

    // k2 with programmatic dependent launch on k1
    {
        cudaLaunchConfig_t cfg = {};
        cfg.gridDim = dim3(B / 8);
        cfg.blockDim = dim3(256);
        cfg.dynamicSmemBytes = K2_BYTES;
        cfg.stream = 0;
        cudaLaunchAttribute at[1];
        at[0].id = cudaLaunchAttributeProgrammaticStreamSerialization;
        at[0].val.programmaticStreamSerializationAllowed = 1;
        cfg.attrs = at;
        cfg.numAttrs = 1;
        cudaLaunchKernelEx(&cfg, k2_attn, state2, b_sur);
    }

    k3_tail<<<B / 64, 256, K3_BYTES>>>(W_j2, b_j2, out);
}